// round 13
// baseline (speedup 1.0000x reference)
#include <cuda_runtime.h>
#include <math.h>

#define LLEN 8192
#define BATCH 256
#define TL 512
#define EPSB 1e-5f
#define NCHUNK 8

typedef unsigned long long u64;

// ---------------- f32x2 helpers ----------------
__device__ __forceinline__ u64 f2(u64 a, u64 b, u64 c) {
    u64 d;
    asm("fma.rn.f32x2 %0, %1, %2, %3;" : "=l"(d) : "l"(a), "l"(b), "l"(c));
    return d;
}
__device__ __forceinline__ u64 pk(float lo, float hi) {
    u64 d;
    asm("mov.b64 %0, {%1, %2};" : "=l"(d) : "f"(lo), "f"(hi));
    return d;
}
__device__ __forceinline__ float lo2(u64 v) {
    float f;
    asm("{.reg .f32 h;\n\tmov.b64 {%0, h}, %1;}" : "=f"(f) : "l"(v));
    return f;
}
__device__ __forceinline__ float hi2(u64 v) {
    float f;
    asm("{.reg .f32 l;\n\tmov.b64 {l, %0}, %1;}" : "=f"(f) : "l"(v));
    return f;
}

// ---------------- device scratch ----------------
__device__ float g_gpart[NCHUNK * BATCH * 256];
__device__ float g_Weff[BATCH * 256];

// ---------------------------------------------------------------------------
// Kernel 1: partial gram of c0. (R12, measured 64us — frozen)
// ---------------------------------------------------------------------------
__global__ __launch_bounds__(256) void gram_kernel(
    const float* __restrict__ x,
    const float* __restrict__ wc1, const float* __restrict__ g1,
    const float* __restrict__ bt1, const float* __restrict__ m1,
    const float* __restrict__ v1)
{
    __shared__ float c0s[16 * 260];
    __shared__ float u1s[64];
    __shared__ float sh1s[16];

    const int b = blockIdx.y;
    const int chunk = blockIdx.x;
    const int t = threadIdx.x;
    const int rp = t >> 6;
    const int cg = (t >> 4) & 3;
    const int p  = t & 15;

    if (t < 16) {
        float inv1 = g1[t] * rsqrtf(v1[t] + EPSB);
        sh1s[t] = bt1[t] - m1[t] * inv1;
        #pragma unroll
        for (int i = 0; i < 4; i++) u1s[t * 4 + i] = inv1 * wc1[t * 4 + i];
    }
    __syncthreads();

    float sh[16];
    #pragma unroll
    for (int i = 0; i < 16; i++) sh[i] = sh1s[i];

    const volatile u64* uv64 = (const volatile u64*)u1s;

    float acc[4][4];
    #pragma unroll
    for (int i = 0; i < 4; i++)
        #pragma unroll
        for (int j = 0; j < 4; j++) acc[i][j] = 0.f;

    for (int ch = 0; ch < 4; ch++) {
        int pos = (chunk * 4 + ch) * 256 + t;
        float xv0 = x[(b * 4 + 0) * LLEN + pos];
        float xv1 = x[(b * 4 + 1) * LLEN + pos];
        float xv2 = x[(b * 4 + 2) * LLEN + pos];
        float xv3 = x[(b * 4 + 3) * LLEN + pos];
        __syncthreads();
        #pragma unroll
        for (int c = 0; c < 16; c++) {
            u64 p01 = uv64[c * 2];
            u64 p23 = uv64[c * 2 + 1];
            float v = sh[c] + lo2(p01) * xv0 + hi2(p01) * xv1
                            + lo2(p23) * xv2 + hi2(p23) * xv3;
            c0s[c * 260 + t] = fmaxf(v, 0.f);
        }
        __syncthreads();
        #pragma unroll
        for (int m = 0; m < 4; m++) {
            int j4 = p + 16 * m;
            float4 ra[4], rb[4];
            #pragma unroll
            for (int i = 0; i < 4; i++)
                ra[i] = ((const float4*)(c0s + (4 * rp + i) * 260))[j4];
            #pragma unroll
            for (int j = 0; j < 4; j++)
                rb[j] = ((const float4*)(c0s + (4 * cg + j) * 260))[j4];
            #pragma unroll
            for (int i = 0; i < 4; i++)
                #pragma unroll
                for (int j = 0; j < 4; j++)
                    acc[i][j] += ra[i].x * rb[j].x + ra[i].y * rb[j].y
                               + ra[i].z * rb[j].z + ra[i].w * rb[j].w;
        }
    }

    #pragma unroll
    for (int i = 0; i < 4; i++)
        #pragma unroll
        for (int j = 0; j < 4; j++) {
            float v = acc[i][j];
            v += __shfl_xor_sync(0xffffffffu, v, 1);
            v += __shfl_xor_sync(0xffffffffu, v, 2);
            v += __shfl_xor_sync(0xffffffffu, v, 4);
            v += __shfl_xor_sync(0xffffffffu, v, 8);
            acc[i][j] = v;
        }
    if (p == 0) {
        float* dst = g_gpart + (chunk * BATCH + b) * 256;
        #pragma unroll
        for (int i = 0; i < 4; i++)
            #pragma unroll
            for (int j = 0; j < 4; j++)
                dst[(4 * rp + i) * 16 + 4 * cg + j] = acc[i][j];
    }
}

// ---------------------------------------------------------------------------
// Kernel 2: sum partials, softmax + fold into W_eff
// ---------------------------------------------------------------------------
__global__ __launch_bounds__(256) void fold_kernel(
    const float* __restrict__ beta_cam,
    const float* __restrict__ wc2, const float* __restrict__ g2,
    const float* __restrict__ v2)
{
    __shared__ float gsm[256];
    __shared__ float asmem[256];
    const int b = blockIdx.x;
    const int t = threadIdx.x;

    float s = 0.f;
    #pragma unroll
    for (int ch = 0; ch < NCHUNK; ch++)
        s += g_gpart[(ch * BATCH + b) * 256 + t];
    gsm[t] = s;
    __syncthreads();

    if (t < 16) {
        float rmin = 1e30f;
        #pragma unroll
        for (int d = 0; d < 16; d++) rmin = fminf(rmin, gsm[t * 16 + d]);
        float e[16];
        float ssum = 0.f;
        #pragma unroll
        for (int d = 0; d < 16; d++) { e[d] = expf(rmin - gsm[t * 16 + d]); ssum += e[d]; }
        float invs = 1.f / ssum;
        #pragma unroll
        for (int d = 0; d < 16; d++) asmem[t * 16 + d] = e[d] * invs;
    }
    __syncthreads();

    const int cg = t >> 4;
    const int dg = t & 15;
    float inv2c = g2[cg] * rsqrtf(v2[cg] + EPSB);
    float beta = beta_cam[0];
    float acc = 0.f;
    #pragma unroll
    for (int e = 0; e < 16; e++) acc += wc2[cg * 16 + e] * asmem[e * 16 + dg];
    g_Weff[b * 256 + t] = inv2c * (beta * acc + wc2[cg * 16 + dg]);
}

// ---------------------------------------------------------------------------
// Kernel 3: fused ConvFusion + attention epilogue.
// 3 CTAs/SM: __launch_bounds__(256,3); phase C in two low-register passes
// (9 then 8 positions/lane, scalar weight broadcasts); phase D packed over
// channel pairs with sequenced wa/wb loads.
// ---------------------------------------------------------------------------
__global__ __launch_bounds__(256, 3) void main_kernel(
    const float* __restrict__ x,
    const float* __restrict__ w00, const float* __restrict__ b00,
    const float* __restrict__ w01, const float* __restrict__ b01,
    const float* __restrict__ w02, const float* __restrict__ b02,
    const float* __restrict__ wc1, const float* __restrict__ g1,
    const float* __restrict__ bt1, const float* __restrict__ m1,
    const float* __restrict__ v1,
    const float* __restrict__ g2, const float* __restrict__ bt2,
    const float* __restrict__ m2, const float* __restrict__ v2,
    float* __restrict__ out)
{
    __shared__ float xs[4 * 580];
    __shared__ float f0s[8 * 544];
    __shared__ float w00s[1024];
    __shared__ float w01t[1024];       // [d][k][c]
    __shared__ float w02t[1024];       // [d][k][c]
    __shared__ float u1s[64];
    __shared__ float sh1s[16];
    __shared__ float sh2s[16];
    __shared__ float weffs[256];
    __shared__ float b00s[8], b01s[8], b02s[8];

    const int t = threadIdx.x;
    const int l0 = blockIdx.x * TL;
    const int b = blockIdx.y;

    // ---- phase A: weights into SMEM ----
    for (int i = t; i < 1024; i += 256) w00s[i] = w00[i];
    for (int i = t; i < 1024; i += 256) {
        int d = i >> 7, k = (i >> 3) & 15, c = i & 7;
        w01t[i] = w01[(c * 8 + d) * 16 + k];
        w02t[i] = w02[(c * 8 + d) * 16 + k];
    }
    if (t < 64) {
        int c = t >> 2;
        float inv1 = g1[c] * rsqrtf(v1[c] + EPSB);
        u1s[t] = inv1 * wc1[t];
    }
    if (t < 16) {
        float inv1 = g1[t] * rsqrtf(v1[t] + EPSB);
        sh1s[t] = bt1[t] - m1[t] * inv1;
        float inv2 = g2[t] * rsqrtf(v2[t] + EPSB);
        sh2s[t] = bt2[t] - m2[t] * inv2;
    }
    weffs[t] = g_Weff[b * 256 + t];
    if (t < 8) { b00s[t] = b00[t]; b01s[t] = b01[t]; b02s[t] = b02[t]; }

    // ---- phase B: x tile (with halo, zero padded) ----
    for (int idx = t; idx < 4 * 580; idx += 256) {
        int i = idx / 580, o = idx - i * 580;
        int g = l0 - 32 + o;
        xs[idx] = (g >= 0 && g < LLEN) ? x[(b * 4 + i) * LLEN + g] : 0.f;
    }
    __syncthreads();

    // ---- phase C: fea0 into SMEM, two low-register passes ----
    {
        const int d = t >> 5;
        const int lane = t & 31;
        const int jj0 = lane * 17;
        const float bv = b00s[d];

        // pass A: 9 positions [jj0, jj0+9)
        {
            float acc[9];
            #pragma unroll
            for (int p = 0; p < 9; p++) acc[p] = 0.f;
            for (int i = 0; i < 4; i++) {
                float xw[40];
                const float* xrow = xs + i * 580 + jj0 + 2;
                #pragma unroll
                for (int m = 0; m < 40; m++) xw[m] = xrow[m];
                const float* wrow = w00s + (d * 4 + i) * 32;
                #pragma unroll
                for (int k = 0; k < 32; k++) {
                    float wv = wrow[k];
                    #pragma unroll
                    for (int p = 0; p < 9; p++) acc[p] += wv * xw[p + k];
                }
            }
            #pragma unroll
            for (int p = 0; p < 9; p++) {
                int jj = jj0 + p;
                int j = l0 - 14 + jj;
                f0s[d * 544 + jj] = (j >= 0 && j <= LLEN) ? (acc[p] + bv) : 0.f;
            }
        }
        // pass B: 8 positions [jj0+9, jj0+17)
        {
            float acc[8];
            #pragma unroll
            for (int p = 0; p < 8; p++) acc[p] = 0.f;
            for (int i = 0; i < 4; i++) {
                float xw[39];
                const float* xrow = xs + i * 580 + jj0 + 11;
                #pragma unroll
                for (int m = 0; m < 39; m++) xw[m] = xrow[m];
                const float* wrow = w00s + (d * 4 + i) * 32;
                #pragma unroll
                for (int k = 0; k < 32; k++) {
                    float wv = wrow[k];
                    #pragma unroll
                    for (int p = 0; p < 8; p++) acc[p] += wv * xw[p + k];
                }
            }
            #pragma unroll
            for (int p = 0; p < 8; p++) {
                int jj = jj0 + 9 + p;
                int j = l0 - 14 + jj;
                f0s[d * 544 + jj] = (j >= 0 && j <= LLEN) ? (acc[p] + bv) : 0.f;
            }
        }
    }
    __syncthreads();

    // ---- phase D: fea1/fea2 packed over channel pairs ----
    {
        const int base2 = 2 * t;
        u64 aA[2][4], aB[2][4];
        #pragma unroll
        for (int c2 = 0; c2 < 4; c2++) {
            u64 bA = pk(b01s[2 * c2], b01s[2 * c2 + 1]);
            u64 bB = pk(b02s[2 * c2], b02s[2 * c2 + 1]);
            aA[0][c2] = bA; aA[1][c2] = bA;
            aB[0][c2] = bB; aB[1][c2] = bB;
        }

        for (int d = 0; d < 8; d++) {
            float win[32];
            const float2* fr = (const float2*)(f0s + d * 544 + base2);
            #pragma unroll
            for (int j2 = 0; j2 < 16; j2++) {
                float2 v = fr[j2];
                win[2 * j2] = v.x; win[2 * j2 + 1] = v.y;
            }
            const longlong2* w1r2 = (const longlong2*)(w01t + d * 128);
            const longlong2* w2r2 = (const longlong2*)(w02t + d * 128);
            #pragma unroll
            for (int k = 0; k < 16; k++) {
                {
                    longlong2 wa0 = w1r2[2 * k];
                    longlong2 wa1 = w1r2[2 * k + 1];
                    u64 fA0 = pk(win[7 + k], win[7 + k]);
                    u64 fA1 = pk(win[8 + k], win[8 + k]);
                    aA[0][0] = f2((u64)wa0.x, fA0, aA[0][0]);
                    aA[0][1] = f2((u64)wa0.y, fA0, aA[0][1]);
                    aA[0][2] = f2((u64)wa1.x, fA0, aA[0][2]);
                    aA[0][3] = f2((u64)wa1.y, fA0, aA[0][3]);
                    aA[1][0] = f2((u64)wa0.x, fA1, aA[1][0]);
                    aA[1][1] = f2((u64)wa0.y, fA1, aA[1][1]);
                    aA[1][2] = f2((u64)wa1.x, fA1, aA[1][2]);
                    aA[1][3] = f2((u64)wa1.y, fA1, aA[1][3]);
                }
                {
                    longlong2 wb0 = w2r2[2 * k];
                    longlong2 wb1 = w2r2[2 * k + 1];
                    u64 fB0 = pk(win[2 * k], win[2 * k]);
                    u64 fB1 = pk(win[2 * k + 1], win[2 * k + 1]);
                    aB[0][0] = f2((u64)wb0.x, fB0, aB[0][0]);
                    aB[0][1] = f2((u64)wb0.y, fB0, aB[0][1]);
                    aB[0][2] = f2((u64)wb1.x, fB0, aB[0][2]);
                    aB[0][3] = f2((u64)wb1.y, fB0, aB[0][3]);
                    aB[1][0] = f2((u64)wb0.x, fB1, aB[1][0]);
                    aB[1][1] = f2((u64)wb0.y, fB1, aB[1][1]);
                    aB[1][2] = f2((u64)wb1.x, fB1, aB[1][2]);
                    aB[1][3] = f2((u64)wb1.y, fB1, aB[1][3]);
                }
            }
        }

        // ---- c0 for both positions, pack over dq pairs ----
        float c0v[2][16];
        #pragma unroll
        for (int p = 0; p < 2; p++) {
            int o = 32 + base2 + p;
            float x0 = xs[0 * 580 + o], x1 = xs[1 * 580 + o];
            float x2 = xs[2 * 580 + o], x3 = xs[3 * 580 + o];
            #pragma unroll
            for (int c = 0; c < 16; c++) {
                float4 u = *(const float4*)(u1s + c * 4);
                float v = sh1s[c] + u.x * x0 + u.y * x1 + u.z * x2 + u.w * x3;
                c0v[p][c] = fmaxf(v, 0.f);
            }
        }
        u64 c0p[2][8];
        #pragma unroll
        for (int p = 0; p < 2; p++)
            #pragma unroll
            for (int q = 0; q < 8; q++)
                c0p[p][q] = pk(c0v[p][2 * q], c0v[p][2 * q + 1]);

        const int l = l0 + base2;
        #pragma unroll
        for (int c = 0; c < 16; c++) {
            const longlong2* wr = (const longlong2*)(weffs + c * 16);
            u64 s0p = pk(sh2s[c], 0.f);
            u64 s1p = pk(sh2s[c], 0.f);
            #pragma unroll
            for (int q2 = 0; q2 < 4; q2++) {
                longlong2 wv = wr[q2];
                s0p = f2((u64)wv.x, c0p[0][2 * q2], s0p);
                s0p = f2((u64)wv.y, c0p[0][2 * q2 + 1], s0p);
                s1p = f2((u64)wv.x, c0p[1][2 * q2], s1p);
                s1p = f2((u64)wv.y, c0p[1][2 * q2 + 1], s1p);
            }
            float s0 = lo2(s0p) + hi2(s0p);
            float s1 = lo2(s1p) + hi2(s1p);
            float f0v, f1v;
            if (c < 8) {
                int c2 = c >> 1;
                f0v = (c & 1) ? hi2(aA[0][c2]) : lo2(aA[0][c2]);
                f1v = (c & 1) ? hi2(aA[1][c2]) : lo2(aA[1][c2]);
            } else {
                int c2 = (c - 8) >> 1;
                f0v = (c & 1) ? hi2(aB[0][c2]) : lo2(aB[0][c2]);
                f1v = (c & 1) ? hi2(aB[1][c2]) : lo2(aB[1][c2]);
                if (l == 0 || l >= LLEN - 2) f0v = 0.f;
                if (l + 1 >= LLEN - 2) f1v = 0.f;
            }
            float2 ov;
            ov.x = f0v + fmaxf(s0, 0.f);
            ov.y = f1v + fmaxf(s1, 0.f);
            *(float2*)(out + (b * 16 + c) * LLEN + l) = ov;
        }
    }
}

// ---------------------------------------------------------------------------
extern "C" void kernel_launch(void* const* d_in, const int* in_sizes, int n_in,
                              void* d_out, int out_size)
{
    const float* x        = (const float*)d_in[0];
    const float* w00      = (const float*)d_in[1];
    const float* b00      = (const float*)d_in[2];
    const float* w01      = (const float*)d_in[3];
    const float* b01      = (const float*)d_in[4];
    const float* w02      = (const float*)d_in[5];
    const float* b02      = (const float*)d_in[6];
    const float* wc1      = (const float*)d_in[7];
    const float* g1       = (const float*)d_in[8];
    const float* bt1      = (const float*)d_in[9];
    const float* m1       = (const float*)d_in[10];
    const float* v1       = (const float*)d_in[11];
    const float* beta_cam = (const float*)d_in[12];
    const float* wc2      = (const float*)d_in[13];
    const float* g2       = (const float*)d_in[14];
    const float* bt2      = (const float*)d_in[15];
    const float* m2       = (const float*)d_in[16];
    const float* v2       = (const float*)d_in[17];
    float* out = (float*)d_out;

    dim3 ggrid(NCHUNK, BATCH);
    gram_kernel<<<ggrid, 256>>>(x, wc1, g1, bt1, m1, v1);
    fold_kernel<<<BATCH, 256>>>(beta_cam, wc2, g2, v2);
    dim3 grid(LLEN / TL, BATCH);
    main_kernel<<<grid, 256>>>(x, w00, b00, w01, b01, w02, b02,
                               wc1, g1, bt1, m1, v1, g2, bt2, m2, v2, out);
}

// round 14
// speedup vs baseline: 1.0122x; 1.0122x over previous
#include <cuda_runtime.h>
#include <math.h>

#define LLEN 8192
#define BATCH 256
#define TL 512
#define EPSB 1e-5f
#define NCHUNK 8

typedef unsigned long long u64;

// ---------------- f32x2 helpers ----------------
__device__ __forceinline__ u64 f2(u64 a, u64 b, u64 c) {
    u64 d;
    asm("fma.rn.f32x2 %0, %1, %2, %3;" : "=l"(d) : "l"(a), "l"(b), "l"(c));
    return d;
}
__device__ __forceinline__ u64 pk(float lo, float hi) {
    u64 d;
    asm("mov.b64 %0, {%1, %2};" : "=l"(d) : "f"(lo), "f"(hi));
    return d;
}
__device__ __forceinline__ float lo2(u64 v) {
    float f;
    asm("{.reg .f32 h;\n\tmov.b64 {%0, h}, %1;}" : "=f"(f) : "l"(v));
    return f;
}
__device__ __forceinline__ float hi2(u64 v) {
    float f;
    asm("{.reg .f32 l;\n\tmov.b64 {l, %0}, %1;}" : "=f"(f) : "l"(v));
    return f;
}

// ---------------- device scratch ----------------
__device__ float g_gpart[NCHUNK * BATCH * 256];

// ---------------------------------------------------------------------------
// Kernel 1: partial gram of c0, SYMMETRIC: only 10 upper-triangle 4x4 tiles.
// pairIdx = t>>4 in [0,16): indices 0..9 map to tile pairs (rp<=cg);
// indices 10..15 idle during accumulation (all threads still compute c0).
// ---------------------------------------------------------------------------
__global__ __launch_bounds__(256) void gram_kernel(
    const float* __restrict__ x,
    const float* __restrict__ wc1, const float* __restrict__ g1,
    const float* __restrict__ bt1, const float* __restrict__ m1,
    const float* __restrict__ v1)
{
    __shared__ float c0s[16 * 260];
    __shared__ float u1s[64];
    __shared__ float sh1s[16];

    const int b = blockIdx.y;
    const int chunk = blockIdx.x;
    const int t = threadIdx.x;
    const int pairIdx = t >> 4;
    const int p  = t & 15;

    // upper-triangle tile pairs: (0,0),(0,1),(0,2),(0,3),(1,1),(1,2),(1,3),(2,2),(2,3),(3,3)
    const int rp = (pairIdx < 4) ? 0 : (pairIdx < 7) ? 1 : (pairIdx < 9) ? 2 : 3;
    const int cg = (pairIdx < 4) ? pairIdx
                 : (pairIdx < 7) ? (pairIdx - 3)
                 : (pairIdx < 9) ? (pairIdx - 5) : 3;
    const bool active = (pairIdx < 10);

    if (t < 16) {
        float inv1 = g1[t] * rsqrtf(v1[t] + EPSB);
        sh1s[t] = bt1[t] - m1[t] * inv1;
        #pragma unroll
        for (int i = 0; i < 4; i++) u1s[t * 4 + i] = inv1 * wc1[t * 4 + i];
    }
    __syncthreads();

    float sh[16];
    #pragma unroll
    for (int i = 0; i < 16; i++) sh[i] = sh1s[i];

    const volatile u64* uv64 = (const volatile u64*)u1s;

    float acc[4][4];
    #pragma unroll
    for (int i = 0; i < 4; i++)
        #pragma unroll
        for (int j = 0; j < 4; j++) acc[i][j] = 0.f;

    for (int ch = 0; ch < 4; ch++) {
        int pos = (chunk * 4 + ch) * 256 + t;
        float xv0 = x[(b * 4 + 0) * LLEN + pos];
        float xv1 = x[(b * 4 + 1) * LLEN + pos];
        float xv2 = x[(b * 4 + 2) * LLEN + pos];
        float xv3 = x[(b * 4 + 3) * LLEN + pos];
        __syncthreads();
        #pragma unroll
        for (int c = 0; c < 16; c++) {
            u64 p01 = uv64[c * 2];
            u64 p23 = uv64[c * 2 + 1];
            float v = sh[c] + lo2(p01) * xv0 + hi2(p01) * xv1
                            + lo2(p23) * xv2 + hi2(p23) * xv3;
            c0s[c * 260 + t] = fmaxf(v, 0.f);
        }
        __syncthreads();
        if (active) {
            #pragma unroll
            for (int m = 0; m < 4; m++) {
                int j4 = p + 16 * m;
                float4 ra[4], rb[4];
                #pragma unroll
                for (int i = 0; i < 4; i++)
                    ra[i] = ((const float4*)(c0s + (4 * rp + i) * 260))[j4];
                #pragma unroll
                for (int j = 0; j < 4; j++)
                    rb[j] = ((const float4*)(c0s + (4 * cg + j) * 260))[j4];
                #pragma unroll
                for (int i = 0; i < 4; i++)
                    #pragma unroll
                    for (int j = 0; j < 4; j++)
                        acc[i][j] += ra[i].x * rb[j].x + ra[i].y * rb[j].y
                                   + ra[i].z * rb[j].z + ra[i].w * rb[j].w;
            }
        }
    }

    #pragma unroll
    for (int i = 0; i < 4; i++)
        #pragma unroll
        for (int j = 0; j < 4; j++) {
            float v = acc[i][j];
            v += __shfl_xor_sync(0xffffffffu, v, 1);
            v += __shfl_xor_sync(0xffffffffu, v, 2);
            v += __shfl_xor_sync(0xffffffffu, v, 4);
            v += __shfl_xor_sync(0xffffffffu, v, 8);
            acc[i][j] = v;
        }
    if (p == 0 && active) {
        float* dst = g_gpart + (chunk * BATCH + b) * 256;
        #pragma unroll
        for (int i = 0; i < 4; i++)
            #pragma unroll
            for (int j = 0; j < 4; j++)
                dst[(4 * rp + i) * 16 + 4 * cg + j] = acc[i][j];
    }
}

// ---------------------------------------------------------------------------
// Kernel 2: fused ConvFusion + attention epilogue, with INLINE fold.
// Main body identical to R12 (best measured, 306us); prolog reconstructs
// symmetric G, does softmax + Weff fold per block (~2us amortized).
// ---------------------------------------------------------------------------
__global__ __launch_bounds__(256) void main_kernel(
    const float* __restrict__ x,
    const float* __restrict__ w00, const float* __restrict__ b00,
    const float* __restrict__ w01, const float* __restrict__ b01,
    const float* __restrict__ w02, const float* __restrict__ b02,
    const float* __restrict__ wc1, const float* __restrict__ g1,
    const float* __restrict__ bt1, const float* __restrict__ m1,
    const float* __restrict__ v1,
    const float* __restrict__ beta_cam,
    const float* __restrict__ wc2,
    const float* __restrict__ g2, const float* __restrict__ bt2,
    const float* __restrict__ m2, const float* __restrict__ v2,
    float* __restrict__ out)
{
    __shared__ float xs[4 * 580];
    __shared__ float f0s[8 * 544];
    __shared__ float w00s[1024];
    __shared__ float w01t[1024];       // [d][k][c]
    __shared__ float w02t[1024];       // [d][k][c]
    __shared__ float u1s[64];
    __shared__ float sh1s[16];
    __shared__ float sh2s[16];
    __shared__ float weffs[256];
    __shared__ float gsm[256];
    __shared__ float asmem[256];
    __shared__ float b00s[8], b01s[8], b02s[8];

    const int t = threadIdx.x;
    const int l0 = blockIdx.x * TL;
    const int b = blockIdx.y;

    // ---- inline fold, step 1: reconstruct symmetric G row entries ----
    {
        int c = t >> 4, dgi = t & 15;
        int ci = c >> 2, dj = dgi >> 2;
        int idx = (ci <= dj) ? (c * 16 + dgi) : (dgi * 16 + c);
        float s = 0.f;
        #pragma unroll
        for (int ch = 0; ch < NCHUNK; ch++)
            s += g_gpart[(ch * BATCH + b) * 256 + idx];
        gsm[t] = s;
    }

    // ---- phase A: weights into SMEM (overlaps with fold syncs) ----
    for (int i = t; i < 1024; i += 256) w00s[i] = w00[i];
    for (int i = t; i < 1024; i += 256) {
        int d = i >> 7, k = (i >> 3) & 15, c = i & 7;
        w01t[i] = w01[(c * 8 + d) * 16 + k];
        w02t[i] = w02[(c * 8 + d) * 16 + k];
    }
    if (t < 64) {
        int c = t >> 2;
        float inv1 = g1[c] * rsqrtf(v1[c] + EPSB);
        u1s[t] = inv1 * wc1[t];
    }
    if (t < 16) {
        float inv1 = g1[t] * rsqrtf(v1[t] + EPSB);
        sh1s[t] = bt1[t] - m1[t] * inv1;
        float inv2 = g2[t] * rsqrtf(v2[t] + EPSB);
        sh2s[t] = bt2[t] - m2[t] * inv2;
    }
    if (t < 8) { b00s[t] = b00[t]; b01s[t] = b01[t]; b02s[t] = b02[t]; }
    __syncthreads();

    // ---- inline fold, step 2: softmax rows ----
    if (t < 16) {
        float rmin = 1e30f;
        #pragma unroll
        for (int d = 0; d < 16; d++) rmin = fminf(rmin, gsm[t * 16 + d]);
        float e[16];
        float ssum = 0.f;
        #pragma unroll
        for (int d = 0; d < 16; d++) { e[d] = expf(rmin - gsm[t * 16 + d]); ssum += e[d]; }
        float invs = 1.f / ssum;
        #pragma unroll
        for (int d = 0; d < 16; d++) asmem[t * 16 + d] = e[d] * invs;
    }

    // ---- phase B: x tile (with halo, zero padded) ----
    for (int idx = t; idx < 4 * 580; idx += 256) {
        int i = idx / 580, o = idx - i * 580;
        int g = l0 - 32 + o;
        xs[idx] = (g >= 0 && g < LLEN) ? x[(b * 4 + i) * LLEN + g] : 0.f;
    }
    __syncthreads();

    // ---- inline fold, step 3: W_eff ----
    {
        int cg_ = t >> 4, dg = t & 15;
        float inv2c = g2[cg_] * rsqrtf(v2[cg_] + EPSB);
        float beta = beta_cam[0];
        float acc = 0.f;
        #pragma unroll
        for (int e = 0; e < 16; e++) acc += wc2[cg_ * 16 + e] * asmem[e * 16 + dg];
        weffs[t] = inv2c * (beta * acc + wc2[cg_ * 16 + dg]);
    }

    // ---- phase C: fea0 into SMEM. warp w owns channel d=w; lane owns 17 pos ----
    {
        const int d = t >> 5;
        const int lane = t & 31;
        const int jj0 = lane * 17;
        float acc[17];
        #pragma unroll
        for (int p = 0; p < 17; p++) acc[p] = 0.f;
        for (int i = 0; i < 4; i++) {
            float xw[48];
            const float* xrow = xs + i * 580 + jj0 + 2;
            #pragma unroll
            for (int m = 0; m < 48; m++) xw[m] = xrow[m];
            const float* wrow = w00s + (d * 4 + i) * 32;
            #pragma unroll
            for (int k = 0; k < 32; k++) {
                float wv = wrow[k];
                #pragma unroll
                for (int p = 0; p < 17; p++) acc[p] += wv * xw[p + k];
            }
        }
        float bv = b00s[d];
        #pragma unroll
        for (int p = 0; p < 17; p++) {
            int jj = jj0 + p;
            int j = l0 - 14 + jj;
            f0s[d * 544 + jj] = (j >= 0 && j <= LLEN) ? (acc[p] + bv) : 0.f;
        }
    }
    __syncthreads();

    // ---- phase D: fea1/fea2 packed over channel pairs ----
    {
        const int base2 = 2 * t;
        u64 aA[2][4], aB[2][4];
        #pragma unroll
        for (int c2 = 0; c2 < 4; c2++) {
            u64 bA = pk(b01s[2 * c2], b01s[2 * c2 + 1]);
            u64 bB = pk(b02s[2 * c2], b02s[2 * c2 + 1]);
            aA[0][c2] = bA; aA[1][c2] = bA;
            aB[0][c2] = bB; aB[1][c2] = bB;
        }

        for (int d = 0; d < 8; d++) {
            float win[32];
            const float2* fr = (const float2*)(f0s + d * 544 + base2);
            #pragma unroll
            for (int j2 = 0; j2 < 16; j2++) {
                float2 v = fr[j2];
                win[2 * j2] = v.x; win[2 * j2 + 1] = v.y;
            }
            const longlong2* w1r2 = (const longlong2*)(w01t + d * 128);
            const longlong2* w2r2 = (const longlong2*)(w02t + d * 128);
            #pragma unroll
            for (int k = 0; k < 16; k++) {
                longlong2 wa0 = w1r2[2 * k];
                longlong2 wa1 = w1r2[2 * k + 1];
                longlong2 wb0 = w2r2[2 * k];
                longlong2 wb1 = w2r2[2 * k + 1];
                u64 fA0 = pk(win[7 + k], win[7 + k]);
                u64 fA1 = pk(win[8 + k], win[8 + k]);
                u64 fB0 = pk(win[2 * k], win[2 * k]);
                u64 fB1 = pk(win[2 * k + 1], win[2 * k + 1]);
                aA[0][0] = f2((u64)wa0.x, fA0, aA[0][0]);
                aA[0][1] = f2((u64)wa0.y, fA0, aA[0][1]);
                aA[0][2] = f2((u64)wa1.x, fA0, aA[0][2]);
                aA[0][3] = f2((u64)wa1.y, fA0, aA[0][3]);
                aA[1][0] = f2((u64)wa0.x, fA1, aA[1][0]);
                aA[1][1] = f2((u64)wa0.y, fA1, aA[1][1]);
                aA[1][2] = f2((u64)wa1.x, fA1, aA[1][2]);
                aA[1][3] = f2((u64)wa1.y, fA1, aA[1][3]);
                aB[0][0] = f2((u64)wb0.x, fB0, aB[0][0]);
                aB[0][1] = f2((u64)wb0.y, fB0, aB[0][1]);
                aB[0][2] = f2((u64)wb1.x, fB0, aB[0][2]);
                aB[0][3] = f2((u64)wb1.y, fB0, aB[0][3]);
                aB[1][0] = f2((u64)wb0.x, fB1, aB[1][0]);
                aB[1][1] = f2((u64)wb0.y, fB1, aB[1][1]);
                aB[1][2] = f2((u64)wb1.x, fB1, aB[1][2]);
                aB[1][3] = f2((u64)wb1.y, fB1, aB[1][3]);
            }
        }

        // ---- c0 for both positions, pack over dq pairs ----
        float c0v[2][16];
        #pragma unroll
        for (int p = 0; p < 2; p++) {
            int o = 32 + base2 + p;
            float x0 = xs[0 * 580 + o], x1 = xs[1 * 580 + o];
            float x2 = xs[2 * 580 + o], x3 = xs[3 * 580 + o];
            #pragma unroll
            for (int c = 0; c < 16; c++) {
                float4 u = *(const float4*)(u1s + c * 4);
                float v = sh1s[c] + u.x * x0 + u.y * x1 + u.z * x2 + u.w * x3;
                c0v[p][c] = fmaxf(v, 0.f);
            }
        }
        u64 c0p[2][8];
        #pragma unroll
        for (int p = 0; p < 2; p++)
            #pragma unroll
            for (int q = 0; q < 8; q++)
                c0p[p][q] = pk(c0v[p][2 * q], c0v[p][2 * q + 1]);

        const int l = l0 + base2;
        #pragma unroll
        for (int c = 0; c < 16; c++) {
            const longlong2* wr = (const longlong2*)(weffs + c * 16);
            u64 s0p = pk(sh2s[c], 0.f);
            u64 s1p = pk(sh2s[c], 0.f);
            #pragma unroll
            for (int q2 = 0; q2 < 4; q2++) {
                longlong2 wv = wr[q2];
                s0p = f2((u64)wv.x, c0p[0][2 * q2], s0p);
                s0p = f2((u64)wv.y, c0p[0][2 * q2 + 1], s0p);
                s1p = f2((u64)wv.x, c0p[1][2 * q2], s1p);
                s1p = f2((u64)wv.y, c0p[1][2 * q2 + 1], s1p);
            }
            float s0 = lo2(s0p) + hi2(s0p);
            float s1 = lo2(s1p) + hi2(s1p);
            float f0v, f1v;
            if (c < 8) {
                int c2 = c >> 1;
                f0v = (c & 1) ? hi2(aA[0][c2]) : lo2(aA[0][c2]);
                f1v = (c & 1) ? hi2(aA[1][c2]) : lo2(aA[1][c2]);
            } else {
                int c2 = (c - 8) >> 1;
                f0v = (c & 1) ? hi2(aB[0][c2]) : lo2(aB[0][c2]);
                f1v = (c & 1) ? hi2(aB[1][c2]) : lo2(aB[1][c2]);
                if (l == 0 || l >= LLEN - 2) f0v = 0.f;
                if (l + 1 >= LLEN - 2) f1v = 0.f;
            }
            float2 ov;
            ov.x = f0v + fmaxf(s0, 0.f);
            ov.y = f1v + fmaxf(s1, 0.f);
            *(float2*)(out + (b * 16 + c) * LLEN + l) = ov;
        }
    }
}

// ---------------------------------------------------------------------------
extern "C" void kernel_launch(void* const* d_in, const int* in_sizes, int n_in,
                              void* d_out, int out_size)
{
    const float* x        = (const float*)d_in[0];
    const float* w00      = (const float*)d_in[1];
    const float* b00      = (const float*)d_in[2];
    const float* w01      = (const float*)d_in[3];
    const float* b01      = (const float*)d_in[4];
    const float* w02      = (const float*)d_in[5];
    const float* b02      = (const float*)d_in[6];
    const float* wc1      = (const float*)d_in[7];
    const float* g1       = (const float*)d_in[8];
    const float* bt1      = (const float*)d_in[9];
    const float* m1       = (const float*)d_in[10];
    const float* v1       = (const float*)d_in[11];
    const float* beta_cam = (const float*)d_in[12];
    const float* wc2      = (const float*)d_in[13];
    const float* g2       = (const float*)d_in[14];
    const float* bt2      = (const float*)d_in[15];
    const float* m2       = (const float*)d_in[16];
    const float* v2       = (const float*)d_in[17];
    float* out = (float*)d_out;

    dim3 ggrid(NCHUNK, BATCH);
    gram_kernel<<<ggrid, 256>>>(x, wc1, g1, bt1, m1, v1);
    dim3 grid(LLEN / TL, BATCH);
    main_kernel<<<grid, 256>>>(x, w00, b00, w01, b01, w02, b02,
                               wc1, g1, bt1, m1, v1, beta_cam, wc2,
                               g2, bt2, m2, v2, out);
}

// round 15
// speedup vs baseline: 1.0381x; 1.0256x over previous
#include <cuda_runtime.h>
#include <math.h>

#define LLEN 8192
#define BATCH 256
#define TL 512
#define EPSB 1e-5f
#define NCHUNK 8

typedef unsigned long long u64;

// ---------------- f32x2 helpers ----------------
__device__ __forceinline__ u64 f2(u64 a, u64 b, u64 c) {
    u64 d;
    asm("fma.rn.f32x2 %0, %1, %2, %3;" : "=l"(d) : "l"(a), "l"(b), "l"(c));
    return d;
}
__device__ __forceinline__ u64 pk(float lo, float hi) {
    u64 d;
    asm("mov.b64 %0, {%1, %2};" : "=l"(d) : "f"(lo), "f"(hi));
    return d;
}
__device__ __forceinline__ float lo2(u64 v) {
    float f;
    asm("{.reg .f32 h;\n\tmov.b64 {%0, h}, %1;}" : "=f"(f) : "l"(v));
    return f;
}
__device__ __forceinline__ float hi2(u64 v) {
    float f;
    asm("{.reg .f32 l;\n\tmov.b64 {l, %0}, %1;}" : "=f"(f) : "l"(v));
    return f;
}

// ---------------- device scratch ----------------
__device__ float g_gpart[NCHUNK * BATCH * 256];
__device__ float g_Weff[BATCH * 256];

// ---------------------------------------------------------------------------
// Kernel 1: partial gram of c0, SYMMETRIC upper-triangle tiles (R14 — kept).
// ---------------------------------------------------------------------------
__global__ __launch_bounds__(256) void gram_kernel(
    const float* __restrict__ x,
    const float* __restrict__ wc1, const float* __restrict__ g1,
    const float* __restrict__ bt1, const float* __restrict__ m1,
    const float* __restrict__ v1)
{
    __shared__ float c0s[16 * 260];
    __shared__ float u1s[64];
    __shared__ float sh1s[16];

    const int b = blockIdx.y;
    const int chunk = blockIdx.x;
    const int t = threadIdx.x;
    const int pairIdx = t >> 4;
    const int p  = t & 15;

    // upper-triangle tile pairs: (0,0),(0,1),(0,2),(0,3),(1,1),(1,2),(1,3),(2,2),(2,3),(3,3)
    const int rp = (pairIdx < 4) ? 0 : (pairIdx < 7) ? 1 : (pairIdx < 9) ? 2 : 3;
    const int cg = (pairIdx < 4) ? pairIdx
                 : (pairIdx < 7) ? (pairIdx - 3)
                 : (pairIdx < 9) ? (pairIdx - 5) : 3;
    const bool active = (pairIdx < 10);

    if (t < 16) {
        float inv1 = g1[t] * rsqrtf(v1[t] + EPSB);
        sh1s[t] = bt1[t] - m1[t] * inv1;
        #pragma unroll
        for (int i = 0; i < 4; i++) u1s[t * 4 + i] = inv1 * wc1[t * 4 + i];
    }
    __syncthreads();

    float sh[16];
    #pragma unroll
    for (int i = 0; i < 16; i++) sh[i] = sh1s[i];

    const volatile u64* uv64 = (const volatile u64*)u1s;

    float acc[4][4];
    #pragma unroll
    for (int i = 0; i < 4; i++)
        #pragma unroll
        for (int j = 0; j < 4; j++) acc[i][j] = 0.f;

    for (int ch = 0; ch < 4; ch++) {
        int pos = (chunk * 4 + ch) * 256 + t;
        float xv0 = x[(b * 4 + 0) * LLEN + pos];
        float xv1 = x[(b * 4 + 1) * LLEN + pos];
        float xv2 = x[(b * 4 + 2) * LLEN + pos];
        float xv3 = x[(b * 4 + 3) * LLEN + pos];
        __syncthreads();
        #pragma unroll
        for (int c = 0; c < 16; c++) {
            u64 p01 = uv64[c * 2];
            u64 p23 = uv64[c * 2 + 1];
            float v = sh[c] + lo2(p01) * xv0 + hi2(p01) * xv1
                            + lo2(p23) * xv2 + hi2(p23) * xv3;
            c0s[c * 260 + t] = fmaxf(v, 0.f);
        }
        __syncthreads();
        if (active) {
            #pragma unroll
            for (int m = 0; m < 4; m++) {
                int j4 = p + 16 * m;
                float4 ra[4], rb[4];
                #pragma unroll
                for (int i = 0; i < 4; i++)
                    ra[i] = ((const float4*)(c0s + (4 * rp + i) * 260))[j4];
                #pragma unroll
                for (int j = 0; j < 4; j++)
                    rb[j] = ((const float4*)(c0s + (4 * cg + j) * 260))[j4];
                #pragma unroll
                for (int i = 0; i < 4; i++)
                    #pragma unroll
                    for (int j = 0; j < 4; j++)
                        acc[i][j] += ra[i].x * rb[j].x + ra[i].y * rb[j].y
                                   + ra[i].z * rb[j].z + ra[i].w * rb[j].w;
            }
        }
    }

    #pragma unroll
    for (int i = 0; i < 4; i++)
        #pragma unroll
        for (int j = 0; j < 4; j++) {
            float v = acc[i][j];
            v += __shfl_xor_sync(0xffffffffu, v, 1);
            v += __shfl_xor_sync(0xffffffffu, v, 2);
            v += __shfl_xor_sync(0xffffffffu, v, 4);
            v += __shfl_xor_sync(0xffffffffu, v, 8);
            acc[i][j] = v;
        }
    if (p == 0 && active) {
        float* dst = g_gpart + (chunk * BATCH + b) * 256;
        #pragma unroll
        for (int i = 0; i < 4; i++)
            #pragma unroll
            for (int j = 0; j < 4; j++)
                dst[(4 * rp + i) * 16 + 4 * cg + j] = acc[i][j];
    }
}

// ---------------------------------------------------------------------------
// Kernel 2: standalone fold — sum partials (with symmetric reconstruction),
// softmax + fold into W_eff. One-shot cost (~8us), off main's critical path.
// ---------------------------------------------------------------------------
__global__ __launch_bounds__(256) void fold_kernel(
    const float* __restrict__ beta_cam,
    const float* __restrict__ wc2, const float* __restrict__ g2,
    const float* __restrict__ v2)
{
    __shared__ float gsm[256];
    __shared__ float asmem[256];
    const int b = blockIdx.x;
    const int t = threadIdx.x;

    {
        int c = t >> 4, dgi = t & 15;
        int ci = c >> 2, dj = dgi >> 2;
        int idx = (ci <= dj) ? (c * 16 + dgi) : (dgi * 16 + c);
        float s = 0.f;
        #pragma unroll
        for (int ch = 0; ch < NCHUNK; ch++)
            s += g_gpart[(ch * BATCH + b) * 256 + idx];
        gsm[t] = s;
    }
    __syncthreads();

    if (t < 16) {
        float rmin = 1e30f;
        #pragma unroll
        for (int d = 0; d < 16; d++) rmin = fminf(rmin, gsm[t * 16 + d]);
        float e[16];
        float ssum = 0.f;
        #pragma unroll
        for (int d = 0; d < 16; d++) { e[d] = expf(rmin - gsm[t * 16 + d]); ssum += e[d]; }
        float invs = 1.f / ssum;
        #pragma unroll
        for (int d = 0; d < 16; d++) asmem[t * 16 + d] = e[d] * invs;
    }
    __syncthreads();

    const int cg = t >> 4;
    const int dg = t & 15;
    float inv2c = g2[cg] * rsqrtf(v2[cg] + EPSB);
    float beta = beta_cam[0];
    float acc = 0.f;
    #pragma unroll
    for (int e = 0; e < 16; e++) acc += wc2[cg * 16 + e] * asmem[e * 16 + dg];
    g_Weff[b * 256 + t] = inv2c * (beta * acc + wc2[cg * 16 + dg]);
}

// ---------------------------------------------------------------------------
// Kernel 3: fused ConvFusion + attention epilogue. (exact R12 main — 306us)
// ---------------------------------------------------------------------------
__global__ __launch_bounds__(256) void main_kernel(
    const float* __restrict__ x,
    const float* __restrict__ w00, const float* __restrict__ b00,
    const float* __restrict__ w01, const float* __restrict__ b01,
    const float* __restrict__ w02, const float* __restrict__ b02,
    const float* __restrict__ wc1, const float* __restrict__ g1,
    const float* __restrict__ bt1, const float* __restrict__ m1,
    const float* __restrict__ v1,
    const float* __restrict__ g2, const float* __restrict__ bt2,
    const float* __restrict__ m2, const float* __restrict__ v2,
    float* __restrict__ out)
{
    __shared__ float xs[4 * 580];
    __shared__ float f0s[8 * 544];
    __shared__ float w00s[1024];
    __shared__ float w01t[1024];       // [d][k][c]
    __shared__ float w02t[1024];       // [d][k][c]
    __shared__ float u1s[64];
    __shared__ float sh1s[16];
    __shared__ float sh2s[16];
    __shared__ float weffs[256];
    __shared__ float b00s[8], b01s[8], b02s[8];

    const int t = threadIdx.x;
    const int l0 = blockIdx.x * TL;
    const int b = blockIdx.y;

    // ---- phase A: weights into SMEM ----
    for (int i = t; i < 1024; i += 256) w00s[i] = w00[i];
    for (int i = t; i < 1024; i += 256) {
        int d = i >> 7, k = (i >> 3) & 15, c = i & 7;
        w01t[i] = w01[(c * 8 + d) * 16 + k];
        w02t[i] = w02[(c * 8 + d) * 16 + k];
    }
    if (t < 64) {
        int c = t >> 2;
        float inv1 = g1[c] * rsqrtf(v1[c] + EPSB);
        u1s[t] = inv1 * wc1[t];
    }
    if (t < 16) {
        float inv1 = g1[t] * rsqrtf(v1[t] + EPSB);
        sh1s[t] = bt1[t] - m1[t] * inv1;
        float inv2 = g2[t] * rsqrtf(v2[t] + EPSB);
        sh2s[t] = bt2[t] - m2[t] * inv2;
    }
    weffs[t] = g_Weff[b * 256 + t];
    if (t < 8) { b00s[t] = b00[t]; b01s[t] = b01[t]; b02s[t] = b02[t]; }

    // ---- phase B: x tile (with halo, zero padded) ----
    for (int idx = t; idx < 4 * 580; idx += 256) {
        int i = idx / 580, o = idx - i * 580;
        int g = l0 - 32 + o;
        xs[idx] = (g >= 0 && g < LLEN) ? x[(b * 4 + i) * LLEN + g] : 0.f;
    }
    __syncthreads();

    // ---- phase C: fea0 into SMEM. warp w owns channel d=w; lane owns 17 pos ----
    {
        const int d = t >> 5;
        const int lane = t & 31;
        const int jj0 = lane * 17;
        float acc[17];
        #pragma unroll
        for (int p = 0; p < 17; p++) acc[p] = 0.f;
        for (int i = 0; i < 4; i++) {
            float xw[48];
            const float* xrow = xs + i * 580 + jj0 + 2;
            #pragma unroll
            for (int m = 0; m < 48; m++) xw[m] = xrow[m];
            const float* wrow = w00s + (d * 4 + i) * 32;
            #pragma unroll
            for (int k = 0; k < 32; k++) {
                float wv = wrow[k];
                #pragma unroll
                for (int p = 0; p < 17; p++) acc[p] += wv * xw[p + k];
            }
        }
        float bv = b00s[d];
        #pragma unroll
        for (int p = 0; p < 17; p++) {
            int jj = jj0 + p;
            int j = l0 - 14 + jj;
            f0s[d * 544 + jj] = (j >= 0 && j <= LLEN) ? (acc[p] + bv) : 0.f;
        }
    }
    __syncthreads();

    // ---- phase D: fea1/fea2 packed over channel pairs ----
    {
        const int base2 = 2 * t;
        u64 aA[2][4], aB[2][4];
        #pragma unroll
        for (int c2 = 0; c2 < 4; c2++) {
            u64 bA = pk(b01s[2 * c2], b01s[2 * c2 + 1]);
            u64 bB = pk(b02s[2 * c2], b02s[2 * c2 + 1]);
            aA[0][c2] = bA; aA[1][c2] = bA;
            aB[0][c2] = bB; aB[1][c2] = bB;
        }

        for (int d = 0; d < 8; d++) {
            float win[32];
            const float2* fr = (const float2*)(f0s + d * 544 + base2);
            #pragma unroll
            for (int j2 = 0; j2 < 16; j2++) {
                float2 v = fr[j2];
                win[2 * j2] = v.x; win[2 * j2 + 1] = v.y;
            }
            const longlong2* w1r2 = (const longlong2*)(w01t + d * 128);
            const longlong2* w2r2 = (const longlong2*)(w02t + d * 128);
            #pragma unroll
            for (int k = 0; k < 16; k++) {
                longlong2 wa0 = w1r2[2 * k];
                longlong2 wa1 = w1r2[2 * k + 1];
                longlong2 wb0 = w2r2[2 * k];
                longlong2 wb1 = w2r2[2 * k + 1];
                u64 fA0 = pk(win[7 + k], win[7 + k]);
                u64 fA1 = pk(win[8 + k], win[8 + k]);
                u64 fB0 = pk(win[2 * k], win[2 * k]);
                u64 fB1 = pk(win[2 * k + 1], win[2 * k + 1]);
                aA[0][0] = f2((u64)wa0.x, fA0, aA[0][0]);
                aA[0][1] = f2((u64)wa0.y, fA0, aA[0][1]);
                aA[0][2] = f2((u64)wa1.x, fA0, aA[0][2]);
                aA[0][3] = f2((u64)wa1.y, fA0, aA[0][3]);
                aA[1][0] = f2((u64)wa0.x, fA1, aA[1][0]);
                aA[1][1] = f2((u64)wa0.y, fA1, aA[1][1]);
                aA[1][2] = f2((u64)wa1.x, fA1, aA[1][2]);
                aA[1][3] = f2((u64)wa1.y, fA1, aA[1][3]);
                aB[0][0] = f2((u64)wb0.x, fB0, aB[0][0]);
                aB[0][1] = f2((u64)wb0.y, fB0, aB[0][1]);
                aB[0][2] = f2((u64)wb1.x, fB0, aB[0][2]);
                aB[0][3] = f2((u64)wb1.y, fB0, aB[0][3]);
                aB[1][0] = f2((u64)wb0.x, fB1, aB[1][0]);
                aB[1][1] = f2((u64)wb0.y, fB1, aB[1][1]);
                aB[1][2] = f2((u64)wb1.x, fB1, aB[1][2]);
                aB[1][3] = f2((u64)wb1.y, fB1, aB[1][3]);
            }
        }

        // ---- c0 for both positions, pack over dq pairs ----
        float c0v[2][16];
        #pragma unroll
        for (int p = 0; p < 2; p++) {
            int o = 32 + base2 + p;
            float x0 = xs[0 * 580 + o], x1 = xs[1 * 580 + o];
            float x2 = xs[2 * 580 + o], x3 = xs[3 * 580 + o];
            #pragma unroll
            for (int c = 0; c < 16; c++) {
                float4 u = *(const float4*)(u1s + c * 4);
                float v = sh1s[c] + u.x * x0 + u.y * x1 + u.z * x2 + u.w * x3;
                c0v[p][c] = fmaxf(v, 0.f);
            }
        }
        u64 c0p[2][8];
        #pragma unroll
        for (int p = 0; p < 2; p++)
            #pragma unroll
            for (int q = 0; q < 8; q++)
                c0p[p][q] = pk(c0v[p][2 * q], c0v[p][2 * q + 1]);

        const int l = l0 + base2;
        #pragma unroll
        for (int c = 0; c < 16; c++) {
            const longlong2* wr = (const longlong2*)(weffs + c * 16);
            u64 s0p = pk(sh2s[c], 0.f);
            u64 s1p = pk(sh2s[c], 0.f);
            #pragma unroll
            for (int q2 = 0; q2 < 4; q2++) {
                longlong2 wv = wr[q2];
                s0p = f2((u64)wv.x, c0p[0][2 * q2], s0p);
                s0p = f2((u64)wv.y, c0p[0][2 * q2 + 1], s0p);
                s1p = f2((u64)wv.x, c0p[1][2 * q2], s1p);
                s1p = f2((u64)wv.y, c0p[1][2 * q2 + 1], s1p);
            }
            float s0 = lo2(s0p) + hi2(s0p);
            float s1 = lo2(s1p) + hi2(s1p);
            float f0v, f1v;
            if (c < 8) {
                int c2 = c >> 1;
                f0v = (c & 1) ? hi2(aA[0][c2]) : lo2(aA[0][c2]);
                f1v = (c & 1) ? hi2(aA[1][c2]) : lo2(aA[1][c2]);
            } else {
                int c2 = (c - 8) >> 1;
                f0v = (c & 1) ? hi2(aB[0][c2]) : lo2(aB[0][c2]);
                f1v = (c & 1) ? hi2(aB[1][c2]) : lo2(aB[1][c2]);
                if (l == 0 || l >= LLEN - 2) f0v = 0.f;
                if (l + 1 >= LLEN - 2) f1v = 0.f;
            }
            float2 ov;
            ov.x = f0v + fmaxf(s0, 0.f);
            ov.y = f1v + fmaxf(s1, 0.f);
            *(float2*)(out + (b * 16 + c) * LLEN + l) = ov;
        }
    }
}

// ---------------------------------------------------------------------------
extern "C" void kernel_launch(void* const* d_in, const int* in_sizes, int n_in,
                              void* d_out, int out_size)
{
    const float* x        = (const float*)d_in[0];
    const float* w00      = (const float*)d_in[1];
    const float* b00      = (const float*)d_in[2];
    const float* w01      = (const float*)d_in[3];
    const float* b01      = (const float*)d_in[4];
    const float* w02      = (const float*)d_in[5];
    const float* b02      = (const float*)d_in[6];
    const float* wc1      = (const float*)d_in[7];
    const float* g1       = (const float*)d_in[8];
    const float* bt1      = (const float*)d_in[9];
    const float* m1       = (const float*)d_in[10];
    const float* v1       = (const float*)d_in[11];
    const float* beta_cam = (const float*)d_in[12];
    const float* wc2      = (const float*)d_in[13];
    const float* g2       = (const float*)d_in[14];
    const float* bt2      = (const float*)d_in[15];
    const float* m2       = (const float*)d_in[16];
    const float* v2       = (const float*)d_in[17];
    float* out = (float*)d_out;

    dim3 ggrid(NCHUNK, BATCH);
    gram_kernel<<<ggrid, 256>>>(x, wc1, g1, bt1, m1, v1);
    fold_kernel<<<BATCH, 256>>>(beta_cam, wc2, g2, v2);
    dim3 grid(LLEN / TL, BATCH);
    main_kernel<<<grid, 256>>>(x, w00, b00, w01, b01, w02, b02,
                               wc1, g1, bt1, m1, v1, g2, bt2, m2, v2, out);
}